// round 3
// baseline (speedup 1.0000x reference)
#include <cuda_runtime.h>
#include <cuda_fp16.h>
#include <math.h>

#define NNODES 50000
#define NEDGES 800000
#define FEAT   120
#define NPB    64          // nodes per block (node kernel)
#define TPB    192         // threads per block (3 groups of 64)
#define PAD    65          // smem column stride (bank-conflict-free transpose)

// Scratch (static __device__ arrays — allocation-free per harness rules)
__device__ __half2 g_qWh[(size_t)NNODES * FEAT * 2]; // [n][f][4 heads as 2x half2], 48 MB
__device__ __half  g_kh [(size_t)NNODES * FEAT];     // 12 MB
__device__ float   g_v  [(size_t)NNODES * FEAT];     // 24 MB
__device__ float   g_z  [NNODES];
__device__ float   g_exp[NEDGES];

__device__ __forceinline__ float normact(float y) {
    float nn = sqrtf(y * y + 1e-10f);
    return (1.0f / (1.0f + expf(-nn))) / nn * y;
}

__device__ __forceinline__ void store_qw(int n, int f, float4 a, float c) {
    __half2 h01 = __floats2half2_rn(a.x * c, a.y * c);
    __half2 h23 = __floats2half2_rn(a.z * c, a.w * c);
    uint2 u;
    u.x = *reinterpret_cast<unsigned*>(&h01);
    u.y = *reinterpret_cast<unsigned*>(&h23);
    reinterpret_cast<uint2*>(g_qWh)[(size_t)n * FEAT + f] = u;
}

// ---------------------------------------------------------------------------
// Node kernel: 64 nodes/block, 192 threads.
//  Phase A: stage x transposed into smem.
//  Phase B: thread-per-node linears (group 0: q -> smem, 1: k -> global fp16,
//           2: v -> g_v + out), weights as warp-uniform float4 broadcasts.
//  Phase D: qW = q x Wd contraction, 2 nodes per warp-iteration.
// ---------------------------------------------------------------------------
__global__ __launch_bounds__(TPB) void node_kernel(
    const float* __restrict__ x,
    const float* __restrict__ Wq0, const float* __restrict__ Wq1, const float* __restrict__ Wq2,
    const float* __restrict__ Wk0, const float* __restrict__ Wk1, const float* __restrict__ Wk2,
    const float* __restrict__ Wv0, const float* __restrict__ Wv1, const float* __restrict__ Wv2,
    const float* __restrict__ Wd0, const float* __restrict__ Wd1, const float* __restrict__ Wd2,
    float* __restrict__ out)
{
    extern __shared__ float smem[];
    float* x_s = smem;                 // [FEAT][PAD]
    float* q_s = smem + FEAT * PAD;    // [FEAT][PAD]

    const int tid  = threadIdx.x;
    const int base = blockIdx.x * NPB;

    // ---- Phase A: load x tile transposed ----
    for (int idx = tid; idx < NPB * FEAT; idx += TPB) {
        int nl = idx / FEAT, f = idx % FEAT;
        int n = base + nl;
        x_s[f * PAD + nl] = (n < NNODES) ? x[(size_t)n * FEAT + f] : 0.0f;
    }
    if (tid < NPB && base + tid < NNODES) g_z[base + tid] = 0.0f;
    __syncthreads();

    // ---- Phase B: thread-per-node linears ----
    {
        const int g  = tid / NPB;   // 0=q, 1=k, 2=v (warp-uniform)
        const int ln = tid % NPB;
        const int n  = base + ln;
        const bool valid = (n < NNODES);

        const float* W0 = (g == 0) ? Wq0 : ((g == 1) ? Wk0 : Wv0);
        const float* W1 = (g == 0) ? Wq1 : ((g == 1) ? Wk1 : Wv1);
        const float* W2 = (g == 0) ? Wq2 : ((g == 1) ? Wk2 : Wv2);

        const float inv_s32 = 0.1767766953f;   // 1/sqrt(32)
        const float inv_s16 = 0.25f;
        const float inv_s8  = 0.3535533906f;   // 1/sqrt(8)

        __half* kp = g_kh + (size_t)n * FEAT;
        float*  vp = g_v  + (size_t)n * FEAT;
        float*  op = out  + (size_t)n * FEAT;

        if (valid) {
            // l=0: 32 in -> 32 out
            {
                float a[32];
                #pragma unroll
                for (int j = 0; j < 32; ++j) a[j] = 0.0f;
                #pragma unroll
                for (int i = 0; i < 32; ++i) {
                    float xi = x_s[i * PAD + ln];
                    const float4* w4p = reinterpret_cast<const float4*>(W0 + i * 32);
                    #pragma unroll
                    for (int jg = 0; jg < 8; ++jg) {
                        float4 w = __ldg(&w4p[jg]);
                        a[4*jg+0] += xi * w.x; a[4*jg+1] += xi * w.y;
                        a[4*jg+2] += xi * w.z; a[4*jg+3] += xi * w.w;
                    }
                }
                #pragma unroll
                for (int j = 0; j < 32; ++j) {
                    float yv = normact(a[j] * inv_s32);
                    if (g == 0)      q_s[j * PAD + ln] = yv;
                    else if (g == 1) kp[j] = __float2half_rn(yv);
                    else             { vp[j] = yv; op[j] = yv; }
                }
            }
            // l=1: 16x3 in -> 16x3 out
            {
                float a[48];
                #pragma unroll
                for (int t = 0; t < 48; ++t) a[t] = 0.0f;
                #pragma unroll
                for (int i = 0; i < 16; ++i) {
                    float x0 = x_s[(32 + i*3 + 0) * PAD + ln];
                    float x1 = x_s[(32 + i*3 + 1) * PAD + ln];
                    float x2 = x_s[(32 + i*3 + 2) * PAD + ln];
                    const float4* w4p = reinterpret_cast<const float4*>(W1 + i * 16);
                    #pragma unroll
                    for (int jg = 0; jg < 4; ++jg) {
                        float4 w = __ldg(&w4p[jg]);
                        int j0 = 4 * jg;
                        a[(j0+0)*3+0] += x0*w.x; a[(j0+0)*3+1] += x1*w.x; a[(j0+0)*3+2] += x2*w.x;
                        a[(j0+1)*3+0] += x0*w.y; a[(j0+1)*3+1] += x1*w.y; a[(j0+1)*3+2] += x2*w.y;
                        a[(j0+2)*3+0] += x0*w.z; a[(j0+2)*3+1] += x1*w.z; a[(j0+2)*3+2] += x2*w.z;
                        a[(j0+3)*3+0] += x0*w.w; a[(j0+3)*3+1] += x1*w.w; a[(j0+3)*3+2] += x2*w.w;
                    }
                }
                #pragma unroll
                for (int j = 0; j < 16; ++j) {
                    float r0 = a[j*3+0]*inv_s16, r1 = a[j*3+1]*inv_s16, r2 = a[j*3+2]*inv_s16;
                    float nn = sqrtf(r0*r0 + r1*r1 + r2*r2 + 1e-10f);
                    float sc = (1.0f / (1.0f + expf(-nn))) / nn;
                    #pragma unroll
                    for (int m = 0; m < 3; ++m) {
                        float yv = sc * ((m == 0) ? r0 : (m == 1) ? r1 : r2);
                        int f = 32 + j*3 + m;
                        if (g == 0)      q_s[f * PAD + ln] = yv;
                        else if (g == 1) kp[f] = __float2half_rn(yv);
                        else             { vp[f] = yv; op[f] = yv; }
                    }
                }
            }
            // l=2: 8x5 in -> 8x5 out
            {
                float a[40];
                #pragma unroll
                for (int t = 0; t < 40; ++t) a[t] = 0.0f;
                #pragma unroll
                for (int i = 0; i < 8; ++i) {
                    float xm[5];
                    #pragma unroll
                    for (int m = 0; m < 5; ++m) xm[m] = x_s[(80 + i*5 + m) * PAD + ln];
                    const float4* w4p = reinterpret_cast<const float4*>(W2 + i * 8);
                    #pragma unroll
                    for (int jg = 0; jg < 2; ++jg) {
                        float4 w = __ldg(&w4p[jg]);
                        int j0 = 4 * jg;
                        #pragma unroll
                        for (int m = 0; m < 5; ++m) {
                            a[(j0+0)*5+m] += xm[m]*w.x; a[(j0+1)*5+m] += xm[m]*w.y;
                            a[(j0+2)*5+m] += xm[m]*w.z; a[(j0+3)*5+m] += xm[m]*w.w;
                        }
                    }
                }
                #pragma unroll
                for (int j = 0; j < 8; ++j) {
                    float ss = 0.0f;
                    float r[5];
                    #pragma unroll
                    for (int m = 0; m < 5; ++m) { r[m] = a[j*5+m]*inv_s8; ss += r[m]*r[m]; }
                    float nn = sqrtf(ss + 1e-10f);
                    float sc = (1.0f / (1.0f + expf(-nn))) / nn;
                    #pragma unroll
                    for (int m = 0; m < 5; ++m) {
                        float yv = sc * r[m];
                        int f = 80 + j*5 + m;
                        if (g == 0)      q_s[f * PAD + ln] = yv;
                        else if (g == 1) kp[f] = __float2half_rn(yv);
                        else             { vp[f] = yv; op[f] = yv; }
                    }
                }
            }
        }
    }
    __syncthreads();

    // ---- Phase D: qW contraction, 2 nodes per warp-iteration ----
    {
        const int warp = tid >> 5;           // 0..5
        const int lane = tid & 31;
        const int nwarps = TPB / 32;
        const float c0 = 0.02176061898f;     // 1/sqrt(2112)
        const float c1 = c0 * 0.5773502692f; // c0/sqrt(3)
        const float c2 = c0 * 0.4472135955f; // c0/sqrt(5)
        const float4* D0 = reinterpret_cast<const float4*>(Wd0);
        const float4* D1 = reinterpret_cast<const float4*>(Wd1);
        const float4* D2 = reinterpret_cast<const float4*>(Wd2);

        for (int p = warp; p < NPB / 2; p += nwarps) {
            const int ln0 = 2*p, ln1 = 2*p + 1;
            const int n0 = base + ln0, n1 = base + ln1;
            const bool v0 = (n0 < NNODES), v1 = (n1 < NNODES);

            // l=0: j = lane
            {
                float4 A0 = make_float4(0.f,0.f,0.f,0.f);
                float4 A1 = make_float4(0.f,0.f,0.f,0.f);
                #pragma unroll
                for (int i = 0; i < 32; ++i) {
                    float4 w = __ldg(&D0[i * 32 + lane]);
                    float q0 = q_s[i * PAD + ln0];
                    float q1 = q_s[i * PAD + ln1];
                    A0.x += q0*w.x; A0.y += q0*w.y; A0.z += q0*w.z; A0.w += q0*w.w;
                    A1.x += q1*w.x; A1.y += q1*w.y; A1.z += q1*w.z; A1.w += q1*w.w;
                }
                if (v0) store_qw(n0, lane, A0, c0);
                if (v1) store_qw(n1, lane, A1, c0);
            }
            // l=1: lanes 0..15, j = lane
            if (lane < 16) {
                float4 B0[3], B1[3];
                #pragma unroll
                for (int m = 0; m < 3; ++m) {
                    B0[m] = make_float4(0.f,0.f,0.f,0.f);
                    B1[m] = make_float4(0.f,0.f,0.f,0.f);
                }
                #pragma unroll
                for (int i = 0; i < 16; ++i) {
                    float4 w = __ldg(&D1[i * 16 + lane]);
                    #pragma unroll
                    for (int m = 0; m < 3; ++m) {
                        float q0 = q_s[(32 + i*3 + m) * PAD + ln0];
                        float q1 = q_s[(32 + i*3 + m) * PAD + ln1];
                        B0[m].x += q0*w.x; B0[m].y += q0*w.y; B0[m].z += q0*w.z; B0[m].w += q0*w.w;
                        B1[m].x += q1*w.x; B1[m].y += q1*w.y; B1[m].z += q1*w.z; B1[m].w += q1*w.w;
                    }
                }
                #pragma unroll
                for (int m = 0; m < 3; ++m) {
                    int f = 32 + lane*3 + m;
                    if (v0) store_qw(n0, f, B0[m], c1);
                    if (v1) store_qw(n1, f, B1[m], c1);
                }
            }
            // l=2: lanes 16..23, j = lane-16
            else if (lane < 24) {
                const int j = lane - 16;
                float4 C0[5], C1[5];
                #pragma unroll
                for (int m = 0; m < 5; ++m) {
                    C0[m] = make_float4(0.f,0.f,0.f,0.f);
                    C1[m] = make_float4(0.f,0.f,0.f,0.f);
                }
                #pragma unroll
                for (int i = 0; i < 8; ++i) {
                    float4 w = __ldg(&D2[i * 8 + j]);
                    #pragma unroll
                    for (int m = 0; m < 5; ++m) {
                        float q0 = q_s[(80 + i*5 + m) * PAD + ln0];
                        float q1 = q_s[(80 + i*5 + m) * PAD + ln1];
                        C0[m].x += q0*w.x; C0[m].y += q0*w.y; C0[m].z += q0*w.z; C0[m].w += q0*w.w;
                        C1[m].x += q1*w.x; C1[m].y += q1*w.y; C1[m].z += q1*w.z; C1[m].w += q1*w.w;
                    }
                }
                #pragma unroll
                for (int m = 0; m < 5; ++m) {
                    int f = 80 + j*5 + m;
                    if (v0) store_qw(n0, f, C0[m], c2);
                    if (v1) store_qw(n1, f, C1[m], c2);
                }
            }
        }
    }
}

// ---------------------------------------------------------------------------
// Kernel 2: per-edge attention score. One warp per edge (fp16 operands).
// ---------------------------------------------------------------------------
__global__ __launch_bounds__(256) void edge_score_kernel(
    const int* __restrict__ dsts, const int* __restrict__ srcs)
{
    const int e = (blockIdx.x * blockDim.x + threadIdx.x) >> 5;
    const int lane = threadIdx.x & 31;
    if (e >= NEDGES) return;
    const int d = dsts[e];
    const int s = srcs[e];

    const uint2*  qw = reinterpret_cast<const uint2*>(g_qWh + (size_t)d * FEAT * 2);
    const __half* kk = g_kh + (size_t)s * FEAT;

    float ax = 0.f, ay = 0.f, az = 0.f, aw = 0.f;
    #pragma unroll
    for (int it = 0; it < 4; ++it) {
        int f = lane + it * 32;
        if (f < FEAT) {
            float kf = __half2float(kk[f]);
            uint2 wv = qw[f];
            float2 p01 = __half22float2(*reinterpret_cast<__half2*>(&wv.x));
            float2 p23 = __half22float2(*reinterpret_cast<__half2*>(&wv.y));
            ax += p01.x * kf; ay += p01.y * kf; az += p23.x * kf; aw += p23.y * kf;
        }
    }
    #pragma unroll
    for (int off = 16; off > 0; off >>= 1) {
        ax += __shfl_xor_sync(0xffffffffu, ax, off);
        ay += __shfl_xor_sync(0xffffffffu, ay, off);
        az += __shfl_xor_sync(0xffffffffu, az, off);
        aw += __shfl_xor_sync(0xffffffffu, aw, off);
    }
    if (lane == 0) {
        float ev = 0.25f * (expf(ax) + expf(ay) + expf(az) + expf(aw));
        g_exp[e] = ev;
        atomicAdd(&g_z[d], ev);
    }
}

// ---------------------------------------------------------------------------
// Kernel 3: per-edge aggregation. out[dst] += sqrt(exp_e / z[dst]) * v[src].
// ---------------------------------------------------------------------------
__global__ __launch_bounds__(256) void edge_agg_kernel(
    const int* __restrict__ dsts, const int* __restrict__ srcs,
    float* __restrict__ out)
{
    const int e = (blockIdx.x * blockDim.x + threadIdx.x) >> 5;
    const int lane = threadIdx.x & 31;
    if (e >= NEDGES) return;
    const int d = dsts[e];
    const int s = srcs[e];

    const float w = sqrtf(g_exp[e] / g_z[d]);

    if (lane < FEAT / 4) {  // 30 lanes
        const float4* vv = reinterpret_cast<const float4*>(g_v + (size_t)s * FEAT);
        float4 v4 = vv[lane];
        float* p = out + (size_t)d * FEAT + lane * 4;
        asm volatile("red.global.add.v4.f32 [%0], {%1, %2, %3, %4};"
                     :: "l"(p), "f"(w * v4.x), "f"(w * v4.y), "f"(w * v4.z), "f"(w * v4.w)
                     : "memory");
    }
}

// ---------------------------------------------------------------------------
extern "C" void kernel_launch(void* const* d_in, const int* in_sizes, int n_in,
                              void* d_out, int out_size)
{
    const float* x   = (const float*)d_in[0];
    const float* Wq0 = (const float*)d_in[1];
    const float* Wq1 = (const float*)d_in[2];
    const float* Wq2 = (const float*)d_in[3];
    const float* Wk0 = (const float*)d_in[4];
    const float* Wk1 = (const float*)d_in[5];
    const float* Wk2 = (const float*)d_in[6];
    const float* Wv0 = (const float*)d_in[7];
    const float* Wv1 = (const float*)d_in[8];
    const float* Wv2 = (const float*)d_in[9];
    const float* Wd0 = (const float*)d_in[10];
    const float* Wd1 = (const float*)d_in[11];
    const float* Wd2 = (const float*)d_in[12];
    const int* edge_dst = (const int*)d_in[13];
    const int* edge_src = (const int*)d_in[14];
    float* out = (float*)d_out;

    const int smem_bytes = 2 * FEAT * PAD * sizeof(float);  // ~62.4 KB
    static bool attr_set = false;
    if (!attr_set) {
        cudaFuncSetAttribute(node_kernel, cudaFuncAttributeMaxDynamicSharedMemorySize, smem_bytes);
        attr_set = true;
    }

    int nblocks1 = (NNODES + NPB - 1) / NPB;
    node_kernel<<<nblocks1, TPB, smem_bytes>>>(x, Wq0, Wq1, Wq2, Wk0, Wk1, Wk2,
                                               Wv0, Wv1, Wv2, Wd0, Wd1, Wd2, out);

    int nblocks2 = (NEDGES + 7) / 8;
    edge_score_kernel<<<nblocks2, 256>>>(edge_dst, edge_src);
    edge_agg_kernel<<<nblocks2, 256>>>(edge_dst, edge_src, out);
}

// round 4
// speedup vs baseline: 1.6969x; 1.6969x over previous
#include <cuda_runtime.h>
#include <cuda_fp16.h>
#include <math.h>

#define NNODES 50000
#define NEDGES 800000
#define FEAT   120

// Scratch (static __device__ arrays — allocation-free per harness rules)
__device__ __half2 g_qWh[(size_t)NNODES * FEAT * 2]; // [n][f][4 heads as 2x half2], 48 MB
__device__ __half  g_kh [(size_t)NNODES * FEAT];     // 12 MB
__device__ float   g_v  [(size_t)NNODES * FEAT];     // 24 MB
__device__ float   g_z  [NNODES];

__device__ __forceinline__ void store_qw(int n, int f, float4 a, float c) {
    __half2 h01 = __floats2half2_rn(a.x * c, a.y * c);
    __half2 h23 = __floats2half2_rn(a.z * c, a.w * c);
    uint2 u;
    u.x = *reinterpret_cast<unsigned*>(&h01);
    u.y = *reinterpret_cast<unsigned*>(&h23);
    reinterpret_cast<uint2*>(g_qWh)[(size_t)n * FEAT + f] = u;
}

// ---------------------------------------------------------------------------
// Node kernel: one warp per 2 nodes, 8 warps (16 nodes) per block.
// 50000 = 16 * 3125 exactly -> no bounds checks.
// Every weight wavefront (linears and Wd) serves 2 nodes; Wd m-loop is inside
// the i-loop so each Wd row loads once.
// ---------------------------------------------------------------------------
__global__ __launch_bounds__(256) void node_kernel(
    const float* __restrict__ x,
    const float* __restrict__ Wq0, const float* __restrict__ Wq1, const float* __restrict__ Wq2,
    const float* __restrict__ Wk0, const float* __restrict__ Wk1, const float* __restrict__ Wk2,
    const float* __restrict__ Wv0, const float* __restrict__ Wv1, const float* __restrict__ Wv2,
    const float* __restrict__ Wd0, const float* __restrict__ Wd1, const float* __restrict__ Wd2,
    float* __restrict__ out)
{
    __shared__ float sX[8][2][FEAT];
    __shared__ float sQ[8][2][FEAT];

    const int warp = threadIdx.x >> 5;
    const int lane = threadIdx.x & 31;
    const int n0 = blockIdx.x * 16 + warp * 2;
    const int n1 = n0 + 1;

    float* xs0 = sX[warp][0];
    float* xs1 = sX[warp][1];
    float* qs0 = sQ[warp][0];
    float* qs1 = sQ[warp][1];

    for (int f = lane; f < FEAT; f += 32) {
        xs0[f] = x[(size_t)n0 * FEAT + f];
        xs1[f] = x[(size_t)n1 * FEAT + f];
        out[(size_t)n0 * FEAT + f] = 0.0f;   // out accumulates edge sums
        out[(size_t)n1 * FEAT + f] = 0.0f;
    }
    if (lane == 0) { g_z[n0] = 0.0f; g_z[n1] = 0.0f; }
    __syncwarp();

    const float inv_s32 = 0.1767766953f;   // 1/sqrt(32)
    const float inv_s16 = 0.25f;
    const float inv_s8  = 0.3535533906f;   // 1/sqrt(8)

    __half* kp0 = g_kh + (size_t)n0 * FEAT;
    __half* kp1 = g_kh + (size_t)n1 * FEAT;
    float*  vp0 = g_v  + (size_t)n0 * FEAT;
    float*  vp1 = g_v  + (size_t)n1 * FEAT;

    #pragma unroll 1
    for (int pass = 0; pass < 3; ++pass) {
        const float* W0 = (pass == 0) ? Wq0 : ((pass == 1) ? Wk0 : Wv0);
        const float* W1 = (pass == 0) ? Wq1 : ((pass == 1) ? Wk1 : Wv1);
        const float* W2 = (pass == 0) ? Wq2 : ((pass == 1) ? Wk2 : Wv2);

        // l=0: output j = lane
        {
            float a0 = 0.f, a1 = 0.f;
            #pragma unroll
            for (int i = 0; i < 32; ++i) {
                float w = __ldg(&W0[i * 32 + lane]);
                a0 += xs0[i] * w;
                a1 += xs1[i] * w;
            }
            a0 *= inv_s32; a1 *= inv_s32;
            float nn0 = sqrtf(a0*a0 + 1e-10f), nn1 = sqrtf(a1*a1 + 1e-10f);
            float y0 = (1.0f / (1.0f + __expf(-nn0))) / nn0 * a0;
            float y1 = (1.0f / (1.0f + __expf(-nn1))) / nn1 * a1;
            if (pass == 0)      { qs0[lane] = y0; qs1[lane] = y1; }
            else if (pass == 1) { kp0[lane] = __float2half_rn(y0); kp1[lane] = __float2half_rn(y1); }
            else                { vp0[lane] = y0; vp1[lane] = y1; }
        }
        // l=1: lanes 0..15, output j = lane
        if (lane < 16) {
            float r0[3], r1[3];
            #pragma unroll
            for (int m = 0; m < 3; ++m) { r0[m] = 0.f; r1[m] = 0.f; }
            #pragma unroll
            for (int i = 0; i < 16; ++i) {
                float w = __ldg(&W1[i * 16 + lane]);
                #pragma unroll
                for (int m = 0; m < 3; ++m) {
                    r0[m] += xs0[32 + i*3 + m] * w;
                    r1[m] += xs1[32 + i*3 + m] * w;
                }
            }
            float ss0 = 0.f, ss1 = 0.f;
            #pragma unroll
            for (int m = 0; m < 3; ++m) {
                r0[m] *= inv_s16; r1[m] *= inv_s16;
                ss0 += r0[m]*r0[m]; ss1 += r1[m]*r1[m];
            }
            float nn0 = sqrtf(ss0 + 1e-10f), nn1 = sqrtf(ss1 + 1e-10f);
            float sc0 = (1.0f / (1.0f + __expf(-nn0))) / nn0;
            float sc1 = (1.0f / (1.0f + __expf(-nn1))) / nn1;
            #pragma unroll
            for (int m = 0; m < 3; ++m) {
                int f = 32 + lane*3 + m;
                float y0 = sc0 * r0[m], y1 = sc1 * r1[m];
                if (pass == 0)      { qs0[f] = y0; qs1[f] = y1; }
                else if (pass == 1) { kp0[f] = __float2half_rn(y0); kp1[f] = __float2half_rn(y1); }
                else                { vp0[f] = y0; vp1[f] = y1; }
            }
        }
        // l=2: lanes 16..23, output j = lane-16
        else if (lane < 24) {
            const int j = lane - 16;
            float r0[5], r1[5];
            #pragma unroll
            for (int m = 0; m < 5; ++m) { r0[m] = 0.f; r1[m] = 0.f; }
            #pragma unroll
            for (int i = 0; i < 8; ++i) {
                float w = __ldg(&W2[i * 8 + j]);
                #pragma unroll
                for (int m = 0; m < 5; ++m) {
                    r0[m] += xs0[80 + i*5 + m] * w;
                    r1[m] += xs1[80 + i*5 + m] * w;
                }
            }
            float ss0 = 0.f, ss1 = 0.f;
            #pragma unroll
            for (int m = 0; m < 5; ++m) {
                r0[m] *= inv_s8; r1[m] *= inv_s8;
                ss0 += r0[m]*r0[m]; ss1 += r1[m]*r1[m];
            }
            float nn0 = sqrtf(ss0 + 1e-10f), nn1 = sqrtf(ss1 + 1e-10f);
            float sc0 = (1.0f / (1.0f + __expf(-nn0))) / nn0;
            float sc1 = (1.0f / (1.0f + __expf(-nn1))) / nn1;
            #pragma unroll
            for (int m = 0; m < 5; ++m) {
                int f = 80 + j*5 + m;
                float y0 = sc0 * r0[m], y1 = sc1 * r1[m];
                if (pass == 0)      { qs0[f] = y0; qs1[f] = y1; }
                else if (pass == 1) { kp0[f] = __float2half_rn(y0); kp1[f] = __float2half_rn(y1); }
                else                { vp0[f] = y0; vp1[f] = y1; }
            }
        }
        __syncwarp();
    }

    // ---- Wd contraction: qW[n][f][4], both nodes share every Wd wavefront ----
    const float c0 = 0.02176061898f;     // 1/sqrt(2112)
    const float c1 = c0 * 0.5773502692f; // c0/sqrt(3)
    const float c2 = c0 * 0.4472135955f; // c0/sqrt(5)
    const float4* D0 = reinterpret_cast<const float4*>(Wd0);
    const float4* D1 = reinterpret_cast<const float4*>(Wd1);
    const float4* D2 = reinterpret_cast<const float4*>(Wd2);

    // l=0: j = lane
    {
        float4 A0 = make_float4(0.f,0.f,0.f,0.f);
        float4 A1 = make_float4(0.f,0.f,0.f,0.f);
        #pragma unroll
        for (int i = 0; i < 32; ++i) {
            float4 w = __ldg(&D0[i * 32 + lane]);
            float q0 = qs0[i], q1 = qs1[i];
            A0.x += q0*w.x; A0.y += q0*w.y; A0.z += q0*w.z; A0.w += q0*w.w;
            A1.x += q1*w.x; A1.y += q1*w.y; A1.z += q1*w.z; A1.w += q1*w.w;
        }
        store_qw(n0, lane, A0, c0);
        store_qw(n1, lane, A1, c0);
    }
    // l=1: lanes 0..15, j = lane
    if (lane < 16) {
        float4 B0[3], B1[3];
        #pragma unroll
        for (int m = 0; m < 3; ++m) {
            B0[m] = make_float4(0.f,0.f,0.f,0.f);
            B1[m] = make_float4(0.f,0.f,0.f,0.f);
        }
        #pragma unroll
        for (int i = 0; i < 16; ++i) {
            float4 w = __ldg(&D1[i * 16 + lane]);
            #pragma unroll
            for (int m = 0; m < 3; ++m) {
                float q0 = qs0[32 + i*3 + m], q1 = qs1[32 + i*3 + m];
                B0[m].x += q0*w.x; B0[m].y += q0*w.y; B0[m].z += q0*w.z; B0[m].w += q0*w.w;
                B1[m].x += q1*w.x; B1[m].y += q1*w.y; B1[m].z += q1*w.z; B1[m].w += q1*w.w;
            }
        }
        #pragma unroll
        for (int m = 0; m < 3; ++m) {
            int f = 32 + lane*3 + m;
            store_qw(n0, f, B0[m], c1);
            store_qw(n1, f, B1[m], c1);
        }
    }
    // l=2: lanes 16..23, j = lane-16
    else if (lane < 24) {
        const int j = lane - 16;
        float4 C0[5], C1[5];
        #pragma unroll
        for (int m = 0; m < 5; ++m) {
            C0[m] = make_float4(0.f,0.f,0.f,0.f);
            C1[m] = make_float4(0.f,0.f,0.f,0.f);
        }
        #pragma unroll
        for (int i = 0; i < 8; ++i) {
            float4 w = __ldg(&D2[i * 8 + j]);
            #pragma unroll
            for (int m = 0; m < 5; ++m) {
                float q0 = qs0[80 + i*5 + m], q1 = qs1[80 + i*5 + m];
                C0[m].x += q0*w.x; C0[m].y += q0*w.y; C0[m].z += q0*w.z; C0[m].w += q0*w.w;
                C1[m].x += q1*w.x; C1[m].y += q1*w.y; C1[m].z += q1*w.z; C1[m].w += q1*w.w;
            }
        }
        #pragma unroll
        for (int m = 0; m < 5; ++m) {
            int f = 80 + j*5 + m;
            store_qw(n0, f, C0[m], c2);
            store_qw(n1, f, C1[m], c2);
        }
    }
}

// ---------------------------------------------------------------------------
// Fused edge kernel: one warp per edge.
// ev = mean_h exp(qW[dst]·k[src]); z[dst] += ev; out[dst] += sqrt(ev)*v[src].
// (sqrt(ev/z) factorizes: rsqrt(z) applied in finalize.)
// ---------------------------------------------------------------------------
__global__ __launch_bounds__(256) void edge_kernel(
    const int* __restrict__ dsts, const int* __restrict__ srcs,
    float* __restrict__ out)
{
    const int e = (blockIdx.x * blockDim.x + threadIdx.x) >> 5;
    const int lane = threadIdx.x & 31;
    if (e >= NEDGES) return;
    const int d = dsts[e];
    const int s = srcs[e];

    const uint2*  qw = reinterpret_cast<const uint2*>(g_qWh + (size_t)d * FEAT * 2);
    const __half* kk = g_kh + (size_t)s * FEAT;

    float ax = 0.f, ay = 0.f, az = 0.f, aw = 0.f;
    #pragma unroll
    for (int it = 0; it < 4; ++it) {
        int f = lane + it * 32;
        if (f < FEAT) {
            float kf = __half2float(kk[f]);
            uint2 wv = qw[f];
            float2 p01 = __half22float2(*reinterpret_cast<__half2*>(&wv.x));
            float2 p23 = __half22float2(*reinterpret_cast<__half2*>(&wv.y));
            ax += p01.x * kf; ay += p01.y * kf; az += p23.x * kf; aw += p23.y * kf;
        }
    }
    #pragma unroll
    for (int off = 16; off > 0; off >>= 1) {
        ax += __shfl_xor_sync(0xffffffffu, ax, off);
        ay += __shfl_xor_sync(0xffffffffu, ay, off);
        az += __shfl_xor_sync(0xffffffffu, az, off);
        aw += __shfl_xor_sync(0xffffffffu, aw, off);
    }
    const float ev = 0.25f * (__expf(ax) + __expf(ay) + __expf(az) + __expf(aw));
    if (lane == 0) atomicAdd(&g_z[d], ev);

    const float w = sqrtf(ev);
    if (lane < FEAT / 4) {  // 30 lanes
        const float4* vv = reinterpret_cast<const float4*>(g_v + (size_t)s * FEAT);
        float4 v4 = vv[lane];
        float* p = out + (size_t)d * FEAT + lane * 4;
        asm volatile("red.global.add.v4.f32 [%0], {%1, %2, %3, %4};"
                     :: "l"(p), "f"(w * v4.x), "f"(w * v4.y), "f"(w * v4.z), "f"(w * v4.w)
                     : "memory");
    }
}

// ---------------------------------------------------------------------------
// Finalize: out = v_node + out * rsqrt(z)   (z==0 -> no edges -> out sum is 0)
// ---------------------------------------------------------------------------
__global__ __launch_bounds__(256) void finalize_kernel(float* __restrict__ out)
{
    const int t = blockIdx.x * blockDim.x + threadIdx.x;
    if (t >= NNODES * (FEAT / 4)) return;
    const int n = t / (FEAT / 4);
    const float zz = g_z[n];
    const float sc = (zz > 0.0f) ? rsqrtf(zz) : 0.0f;
    float4 o = reinterpret_cast<float4*>(out)[t];
    float4 v = reinterpret_cast<const float4*>(g_v)[t];
    o.x = v.x + o.x * sc;
    o.y = v.y + o.y * sc;
    o.z = v.z + o.z * sc;
    o.w = v.w + o.w * sc;
    reinterpret_cast<float4*>(out)[t] = o;
}

// ---------------------------------------------------------------------------
extern "C" void kernel_launch(void* const* d_in, const int* in_sizes, int n_in,
                              void* d_out, int out_size)
{
    const float* x   = (const float*)d_in[0];
    const float* Wq0 = (const float*)d_in[1];
    const float* Wq1 = (const float*)d_in[2];
    const float* Wq2 = (const float*)d_in[3];
    const float* Wk0 = (const float*)d_in[4];
    const float* Wk1 = (const float*)d_in[5];
    const float* Wk2 = (const float*)d_in[6];
    const float* Wv0 = (const float*)d_in[7];
    const float* Wv1 = (const float*)d_in[8];
    const float* Wv2 = (const float*)d_in[9];
    const float* Wd0 = (const float*)d_in[10];
    const float* Wd1 = (const float*)d_in[11];
    const float* Wd2 = (const float*)d_in[12];
    const int* edge_dst = (const int*)d_in[13];
    const int* edge_src = (const int*)d_in[14];
    float* out = (float*)d_out;

    // Node kernel: 16 nodes/block (2 per warp), 50000/16 = 3125 blocks exactly
    node_kernel<<<NNODES / 16, 256>>>(x, Wq0, Wq1, Wq2, Wk0, Wk1, Wk2,
                                      Wv0, Wv1, Wv2, Wd0, Wd1, Wd2, out);

    // Fused edge kernel: 8 edges/block (one warp each)
    edge_kernel<<<(NEDGES + 7) / 8, 256>>>(edge_dst, edge_src, out);

    // Finalize: one thread per float4 of out
    const int nt = NNODES * (FEAT / 4);
    finalize_kernel<<<(nt + 255) / 256, 256>>>(out);
}